// round 2
// baseline (speedup 1.0000x reference)
#include <cuda_runtime.h>
#include <math.h>
#include <stdint.h>

// Problem constants (fixed shapes)
#define NN 100000
#define EE 1000000
#define F_IN 64
#define EMB 32
#define HH 4
#define CC 32
#define HCC 128
#define NEG_SLOPE 0.2f

// ---------------- scratch (device globals; no allocation allowed) ----------
__device__ float g_h [(size_t)NN * HCC];
__device__ float g_xl[(size_t)NN * HCC];
__device__ float g_xr[(size_t)NN * HCC];
__device__ float g_sk[(size_t)NN * HCC];
__device__ int   g_deg[NN];
__device__ int   g_rowptr[NN + 1];
__device__ int   g_cursor[NN];
__device__ int   g_csr[EE];

// ---------------- small utility kernels -----------------------------------
__global__ void zero_int_kernel(int* p, int n) {
    int i = blockIdx.x * blockDim.x + threadIdx.x;
    if (i < n) p[i] = 0;
}

__global__ void hist_kernel(const int* __restrict__ dst, int* __restrict__ deg, int e) {
    int i = blockIdx.x * blockDim.x + threadIdx.x;
    if (i < e) atomicAdd(&deg[dst[i]], 1);
}

// single-block exclusive scan over deg -> rowptr (+cursor copy), rowptr[n]=total
__global__ void scan_kernel(const int* __restrict__ deg, int* __restrict__ rowptr,
                            int* __restrict__ cursor, int n) {
    __shared__ int sums[1024];
    int tid = threadIdx.x;
    int chunk = (n + 1023) / 1024;
    int start = tid * chunk;
    int end   = min(start + chunk, n);
    int s = 0;
    for (int i = start; i < end; ++i) s += deg[i];
    sums[tid] = s;
    __syncthreads();
    // Hillis-Steele inclusive scan
    for (int off = 1; off < 1024; off <<= 1) {
        int v = 0;
        if (tid >= off) v = sums[tid - off];
        __syncthreads();
        if (tid >= off) sums[tid] += v;
        __syncthreads();
    }
    int prefix = (tid == 0) ? 0 : sums[tid - 1];
    for (int i = start; i < end; ++i) {
        rowptr[i] = prefix;
        cursor[i] = prefix;
        prefix += deg[i];
    }
    if (tid == 1023) rowptr[n] = sums[1023];
}

__global__ void scatter_kernel(const int* __restrict__ src, const int* __restrict__ dst,
                               int* __restrict__ cursor, int* __restrict__ csr, int e) {
    int i = blockIdx.x * blockDim.x + threadIdx.x;
    if (i < e) {
        int d = dst[i];
        int pos = atomicAdd(&cursor[d], 1);
        csr[pos] = src[i];
    }
}

// ---------------- tiled SGEMM: C[M,Nc] = A[M,K] @ W[K,Nc] + bias -----------
#define BM 128
#define BN 128
#define BK 16
#define TM 8
#define TN 8

__global__ __launch_bounds__(256, 2)
void gemm_bias_kernel(const float* __restrict__ A, const float* __restrict__ W,
                      const float* __restrict__ bias, float* __restrict__ C,
                      int M, int K, int Nc, int doRelu) {
    __shared__ float As[BK][BM + 4];
    __shared__ float Bs[BK][BN];

    int bm = blockIdx.x * BM;
    int bn = blockIdx.y * BN;
    int tid = threadIdx.x;
    int tx = tid & 15;        // 0..15 -> n
    int ty = tid >> 4;        // 0..15 -> m

    float acc[TM][TN];
#pragma unroll
    for (int i = 0; i < TM; ++i)
#pragma unroll
        for (int j = 0; j < TN; ++j) acc[i][j] = 0.f;

    for (int k0 = 0; k0 < K; k0 += BK) {
        // load A tile (BM x BK), guard M
#pragma unroll
        for (int i = tid; i < BM * BK; i += 256) {
            int r = i / BK, c = i % BK;
            int gm = bm + r;
            As[c][r] = (gm < M) ? A[(size_t)gm * K + (k0 + c)] : 0.f;
        }
        // load B tile (BK x BN), guard Nc
#pragma unroll
        for (int i = tid; i < BK * BN; i += 256) {
            int r = i / BN, c = i % BN;
            int gn = bn + c;
            Bs[r][c] = (gn < Nc) ? W[(size_t)(k0 + r) * Nc + gn] : 0.f;
        }
        __syncthreads();

#pragma unroll
        for (int kk = 0; kk < BK; ++kk) {
            float a[TM], b[TN];
            const float4* av = reinterpret_cast<const float4*>(&As[kk][ty * TM]);
            const float4* bv = reinterpret_cast<const float4*>(&Bs[kk][tx * TN]);
            float4 a0 = av[0], a1 = av[1];
            float4 b0 = bv[0], b1 = bv[1];
            a[0]=a0.x; a[1]=a0.y; a[2]=a0.z; a[3]=a0.w;
            a[4]=a1.x; a[5]=a1.y; a[6]=a1.z; a[7]=a1.w;
            b[0]=b0.x; b[1]=b0.y; b[2]=b0.z; b[3]=b0.w;
            b[4]=b1.x; b[5]=b1.y; b[6]=b1.z; b[7]=b1.w;
#pragma unroll
            for (int i = 0; i < TM; ++i)
#pragma unroll
                for (int j = 0; j < TN; ++j) acc[i][j] += a[i] * b[j];
        }
        __syncthreads();
    }

#pragma unroll
    for (int i = 0; i < TM; ++i) {
        int gm = bm + ty * TM + i;
        if (gm >= M) continue;
#pragma unroll
        for (int j = 0; j < TN; ++j) {
            int gn = bn + tx * TN + j;
            if (gn >= Nc) continue;
            float v = acc[i][j] + (bias ? bias[gn] : 0.f);
            if (doRelu) v = fmaxf(v, 0.f);
            C[(size_t)gm * Nc + gn] = v;
        }
    }
}

// ---------------- GAT edge kernel: one warp per dst node, online softmax ---
__global__ __launch_bounds__(256)
void gat_edge_kernel(const int* __restrict__ rowptr, const int* __restrict__ csr,
                     const float* __restrict__ xl, const float* __restrict__ xr,
                     const float* __restrict__ skip,
                     const float* __restrict__ att, const float* __restrict__ cb,
                     float* __restrict__ out, int n, int doRelu, int doNorm) {
    int warp_id = (blockIdx.x * blockDim.x + threadIdx.x) >> 5;
    if (warp_id >= n) return;
    int lane = threadIdx.x & 31;
    int node = warp_id;

    float xrv[HH], attv[HH];
#pragma unroll
    for (int h = 0; h < HH; ++h) {
        xrv[h]  = __ldg(&xr[(size_t)node * HCC + h * CC + lane]);
        attv[h] = __ldg(&att[h * CC + lane]);
    }

    float m[HH], den[HH], acc[HH];
#pragma unroll
    for (int h = 0; h < HH; ++h) { m[h] = -INFINITY; den[h] = 0.f; acc[h] = 0.f; }

    int e0 = rowptr[node];
    int e1 = rowptr[node + 1];
    for (int e = e0; e < e1; ++e) {
        int src = csr[e];
        float xlv[HH], s[HH];
#pragma unroll
        for (int h = 0; h < HH; ++h)
            xlv[h] = __ldg(&xl[(size_t)src * HCC + h * CC + lane]);
#pragma unroll
        for (int h = 0; h < HH; ++h) {
            float t = xlv[h] + xrv[h];
            t = (t > 0.f) ? t : NEG_SLOPE * t;
            s[h] = t * attv[h];
        }
        // warp-reduce score per head
#pragma unroll
        for (int off = 16; off > 0; off >>= 1) {
#pragma unroll
            for (int h = 0; h < HH; ++h)
                s[h] += __shfl_xor_sync(0xffffffffu, s[h], off);
        }
        // online softmax update
#pragma unroll
        for (int h = 0; h < HH; ++h) {
            float nm = fmaxf(m[h], s[h]);
            float scale = __expf(m[h] - nm);   // exp(-inf)=0 on first edge
            float p = __expf(s[h] - nm);
            den[h] = den[h] * scale + p;
            acc[h] = acc[h] * scale + p * xlv[h];
            m[h] = nm;
        }
    }

    float o[HH];
#pragma unroll
    for (int h = 0; h < HH; ++h) {
        float g = (den[h] > 0.f) ? (acc[h] / den[h]) : 0.f;
        o[h] = g + __ldg(&cb[h * CC + lane]) + skip[(size_t)node * HCC + h * CC + lane];
        if (doRelu) o[h] = fmaxf(o[h], 0.f);
    }
    if (doNorm) {
        float sq = 0.f;
#pragma unroll
        for (int h = 0; h < HH; ++h) sq += o[h] * o[h];
#pragma unroll
        for (int off = 16; off > 0; off >>= 1)
            sq += __shfl_xor_sync(0xffffffffu, sq, off);
        float inv = rsqrtf(sq);
#pragma unroll
        for (int h = 0; h < HH; ++h) o[h] *= inv;
    }
#pragma unroll
    for (int h = 0; h < HH; ++h)
        out[(size_t)node * HCC + h * CC + lane] = o[h];
}

// ---------------- host ------------------------------------------------------
extern "C" void kernel_launch(void* const* d_in, const int* in_sizes, int n_in,
                              void* d_out, int out_size) {
    const float* x  = (const float*)d_in[0];
    const int*   ei = (const int*)d_in[1];
    const float* W0 = (const float*)d_in[2];

    // f: 3..10, m: 11..18, l: 19..26 (order: Wl, bl, Wr, br, att, cb, Ws, bs)
    const float* P[27];
    for (int i = 3; i < 27; ++i) P[i] = (const float*)d_in[i];

    float *h, *xl, *xr, *sk;
    int *deg, *rowptr, *cursor, *csr;
    cudaGetSymbolAddress((void**)&h,      g_h);
    cudaGetSymbolAddress((void**)&xl,     g_xl);
    cudaGetSymbolAddress((void**)&xr,     g_xr);
    cudaGetSymbolAddress((void**)&sk,     g_sk);
    cudaGetSymbolAddress((void**)&deg,    g_deg);
    cudaGetSymbolAddress((void**)&rowptr, g_rowptr);
    cudaGetSymbolAddress((void**)&cursor, g_cursor);
    cudaGetSymbolAddress((void**)&csr,    g_csr);

    const int* src = ei;
    const int* dst = ei + EE;

    // ---- CSR build (by dst) ----
    zero_int_kernel<<<(NN + 255) / 256, 256>>>(deg, NN);
    hist_kernel<<<(EE + 255) / 256, 256>>>(dst, deg, EE);
    scan_kernel<<<1, 1024>>>(deg, rowptr, cursor, NN);
    scatter_kernel<<<(EE + 255) / 256, 256>>>(src, dst, cursor, csr, EE);

    dim3 gemm_grid((NN + BM - 1) / BM, 1);

    // h0 = relu(x @ W0)  [N, 32], packed stride 32 in g_h
    gemm_bias_kernel<<<gemm_grid, 256>>>(x, W0, nullptr, h, NN, F_IN, EMB, 1);

    int edge_blocks = (NN * 32 + 255) / 256;

    // layer runner
    auto run_layer = [&](int base, int K, int doRelu, int doNorm, float* outp) {
        const float* Wl  = P[base + 0];
        const float* bl  = P[base + 1];
        const float* Wr  = P[base + 2];
        const float* br  = P[base + 3];
        const float* att = P[base + 4];
        const float* cb  = P[base + 5];
        const float* Ws  = P[base + 6];
        const float* bs  = P[base + 7];
        gemm_bias_kernel<<<gemm_grid, 256>>>(h, Wl, bl, xl, NN, K, HCC, 0);
        gemm_bias_kernel<<<gemm_grid, 256>>>(h, Wr, br, xr, NN, K, HCC, 0);
        gemm_bias_kernel<<<gemm_grid, 256>>>(h, Ws, bs, sk, NN, K, HCC, 0);
        gat_edge_kernel<<<edge_blocks, 256>>>(rowptr, csr, xl, xr, sk, att, cb,
                                              outp, NN, doRelu, doNorm);
    };

    run_layer(3,  EMB, 1, 0, h);          // first layer (K=32)
    run_layer(11, HCC, 1, 0, h);          // mid x3 (shared weights)
    run_layer(11, HCC, 1, 0, h);
    run_layer(11, HCC, 1, 0, h);
    run_layer(19, HCC, 0, 1, (float*)d_out);  // last layer + L2 normalize
}